// round 9
// baseline (speedup 1.0000x reference)
#include <cuda_runtime.h>
#include <cuda_bf16.h>

// LocalLoadBalancingLoss: B=65536, T=792, D=99, L=16.
// loss = mean_b[ var_{ddof=1}(u_b) + 0.5 * max(u_b) ], u = linkTraffic/(cap+1e-8)
//
// R9: ROWS=32, 1024 thr, 2 blocks/SM. Warp = (link, segment-half), lane = row:
// every phase-B LDS is a full 128B conflict-free wavefront. CSR entries are
// pre-packed byte offsets (pred<<16 | dem) so per-entry work is 2 IADD+2 LDS+FFMA.

#define NUM_T 792
#define NUM_D 99
#define NUM_L 16
#define ROWS 32
#define THREADS 1024
#define PST 793                 // odd stride -> conflict-free LDS across rows
#define MAX_BLOCKS 2048
#define SETUP_THREADS 800

__device__ unsigned g_poff[NUM_T];      // (pred_byte_off << 16) | dem_byte_off, link-sorted
__device__ int      g_off[NUM_L + 1];
__device__ float    g_partials[MAX_BLOCKS];
__device__ unsigned g_done;

__device__ __forceinline__ void cpa4(unsigned dst, const float* src) {
    asm volatile("cp.async.ca.shared.global [%0], [%1], 4;" :: "r"(dst), "l"(src));
}

// ---------------------------------------------------------------------------
// Setup: link-sorted CSR of packed byte offsets.
// ---------------------------------------------------------------------------
__global__ void llb_setup_kernel(const int* __restrict__ t2l) {
    __shared__ int s_wcnt[25][NUM_L];
    __shared__ int s_tot[NUM_L];
    __shared__ int s_off[NUM_L + 1];

    const int tid  = threadIdx.x;       // 800 = 25 warps
    const int w    = tid >> 5;
    const int lane = tid & 31;
    const bool act = (tid < NUM_T);

    if (tid < 25 * NUM_L) ((int*)s_wcnt)[tid] = 0;

    const int l = act ? t2l[tid] : 0;
    const int val = act ? l : (100 + lane);     // idle lanes -> singleton groups
    __syncthreads();

    unsigned m = __match_any_sync(0xFFFFFFFFu, val);
    const int rank = __popc(m & ((1u << lane) - 1u));
    if (act && lane == (__ffs(m) - 1)) s_wcnt[w][l] = __popc(m);
    __syncthreads();

    if (tid < NUM_L) {
        int acc = 0;
        for (int ww = 0; ww < 25; ww++) {
            int c = s_wcnt[ww][tid];
            s_wcnt[ww][tid] = acc;               // exclusive prefix over warps
            acc += c;
        }
        s_tot[tid] = acc;
    }
    __syncthreads();

    if (tid == 0) {
        int a = 0;
        for (int ll = 0; ll < NUM_L; ll++) { s_off[ll] = a; a += s_tot[ll]; }
        s_off[NUM_L] = a;                        // == 792
    }
    __syncthreads();

    if (act) {
        unsigned pk = ((unsigned)(tid * 4) << 16) | (unsigned)((tid >> 3) * 4);
        g_poff[s_off[l] + s_wcnt[w][l] + rank] = pk;
    }
    if (tid <= NUM_L) g_off[tid] = s_off[tid];
}

// ---------------------------------------------------------------------------
// Main: 2048 blocks x 32 rows, 1024 threads, 2 blocks/SM.
// ---------------------------------------------------------------------------
__global__ __launch_bounds__(THREADS, 2)
void llb_main_kernel(const float* __restrict__ pred,
                     const float* __restrict__ dem,
                     const float* __restrict__ cap,
                     float* __restrict__ out,
                     float inv_batch) {
    extern __shared__ float smem[];
    float* sp = smem;                    // [32][793]
    float* sd = smem + ROWS * PST;       // [32][99]; later overlaid as su[16][64]
    __shared__ int sflag;

    const int tid  = threadIdx.x;
    const int w    = tid >> 5;           // warp = link*2 + part
    const int lane = tid & 31;           // row
    const int link = w >> 1;
    const int part = w & 1;

    // metadata early (L2 latency overlaps staging)
    const int   beg  = g_off[link];
    const int   end  = g_off[link + 1];
    const float invc = 1.0f / (cap[link] + 1e-8f);
    const int   len  = end - beg;
    const int   len0 = (len + 1) >> 1;
    const int   mybeg = beg + (part ? len0 : 0);
    const int   mycnt = part ? (len - len0) : len0;

    const long long tile = blockIdx.x;
    const float* gp = pred + tile * (ROWS * NUM_T);
    const float* gd = dem  + tile * (ROWS * NUM_D);
    const unsigned spA = (unsigned)__cvta_generic_to_shared(sp);
    const unsigned sdA = (unsigned)__cvta_generic_to_shared(sd);

    // ---- stage-in (coalesced global; smem stride 793 keeps phase B clean) ----
    #pragma unroll
    for (int k = 0; k < 25; k++) {
        int i = tid + k * THREADS;
        if (i < ROWS * NUM_T) {
            int rr = (unsigned)i / NUM_T;        // smem idx = i + rr (stride 793)
            cpa4(spA + 4u * (unsigned)(i + rr), gp + i);
        }
    }
    #pragma unroll
    for (int k = 0; k < 4; k++) {
        int i = tid + k * THREADS;
        if (i < ROWS * NUM_D) cpa4(sdA + 4u * (unsigned)i, gd + i);
    }
    asm volatile("cp.async.commit_group;");
    asm volatile("cp.async.wait_group 0;");
    __syncthreads();

    // ---- phase B: warp walks its half-segment; lane = row (full 128B LDS) ----
    const char* pr = (const char*)(sp + lane * PST);
    const char* dm = (const char*)(sd + lane * NUM_D);
    const unsigned* ix = g_poff + mybeg;

    float s0 = 0.f, s1 = 0.f;
    int i = 0;
    for (; i + 1 < mycnt; i += 2) {
        unsigned p0 = __ldg(ix + i);
        unsigned p1 = __ldg(ix + i + 1);
        s0 += *(const float*)(pr + (p0 >> 16)) * *(const float*)(dm + (p0 & 0xFFFFu));
        s1 += *(const float*)(pr + (p1 >> 16)) * *(const float*)(dm + (p1 & 0xFFFFu));
    }
    if (i < mycnt) {
        unsigned p0 = __ldg(ix + i);
        s0 += *(const float*)(pr + (p0 >> 16)) * *(const float*)(dm + (p0 & 0xFFFFu));
    }
    const float u = (s0 + s1) * invc;

    __syncthreads();                     // all sd reads done -> overlay su
    float* su = sd;                      // [16 links][2 parts][32 rows]
    su[w * 32 + lane] = u;               // == su[link*64 + part*32 + row]
    __syncthreads();

    // ---- per-row stats: warp 0, lane = row ----
    float pv = 0.f;
    if (w == 0) {
        float sum = 0.f, mx = -1e30f;
        #pragma unroll
        for (int l = 0; l < NUM_L; l++) {
            float x = su[l * 64 + lane] + su[l * 64 + 32 + lane];
            sum += x;
            mx = fmaxf(mx, x);
        }
        const float mean = sum * (1.0f / NUM_L);
        float var = 0.f;
        #pragma unroll
        for (int l = 0; l < NUM_L; l++) {
            float x = su[l * 64 + lane] + su[l * 64 + 32 + lane];
            float d = x - mean;
            var += d * d;
        }
        var *= (1.0f / (NUM_L - 1));             // ddof = 1
        pv = var + 0.5f * mx;
        #pragma unroll
        for (int o = 16; o > 0; o >>= 1)
            pv += __shfl_down_sync(0xFFFFFFFFu, pv, o);
    }
    if (tid == 0) g_partials[blockIdx.x] = pv;

    // ---- fused deterministic reduction: last block, fixed-order tree ----
    __threadfence();
    if (tid == 0) {
        unsigned n = atomicAdd(&g_done, 1u);
        sflag = (n == (unsigned)(gridDim.x - 1)) ? 1 : 0;
    }
    __syncthreads();
    if (sflag) {
        __threadfence();
        float v = g_partials[tid] + g_partials[tid + THREADS];   // fixed order
        float* rb = sp;                          // reuse smem
        rb[tid] = v;
        __syncthreads();
        #pragma unroll
        for (int s = THREADS / 2; s > 0; s >>= 1) {
            if (tid < s) rb[tid] += rb[tid + s]; // fixed pairing -> deterministic
            __syncthreads();
        }
        if (tid == 0) {
            out[0] = rb[0] * inv_batch;
            g_done = 0;                          // reset for next graph replay
        }
    }
}

extern "C" void kernel_launch(void* const* d_in, const int* in_sizes, int n_in,
                              void* d_out, int out_size) {
    const float* pred = (const float*)d_in[0];   // [B, 792]
    const float* dem  = (const float*)d_in[1];   // [B, 99]
    const int*   t2l  = (const int*)d_in[2];     // [792]
    const float* cap  = (const float*)d_in[3];   // [16]
    float* out = (float*)d_out;

    const int B = in_sizes[1] / NUM_D;           // 65536
    const int ntiles = B / ROWS;                 // 2048

    static bool attr_set = false;
    const int smem_bytes = (ROWS * PST + ROWS * NUM_D) * (int)sizeof(float); // 114176
    if (!attr_set) {
        cudaFuncSetAttribute(llb_main_kernel,
                             cudaFuncAttributeMaxDynamicSharedMemorySize, smem_bytes);
        attr_set = true;
    }

    llb_setup_kernel<<<1, SETUP_THREADS>>>(t2l);
    llb_main_kernel<<<ntiles, THREADS, smem_bytes>>>(pred, dem, cap, out,
                                                     1.0f / (float)B);
}